// round 15
// baseline (speedup 1.0000x reference)
#include <cuda_runtime.h>
#include <cuda_fp16.h>
#include <stdint.h>
#include <math.h>

#define BB 4
#define TT 2048
#define CC 512
#define HH 8
#define DD 64
#define BT (BB*TT)
#define WP 72   // fp16 smem pitch for 64-wide tiles (144B rows: 16B aligned)

typedef __half  f16;

// -------- scratch (static device globals; no allocations allowed) --------
__device__ f16   g_hb [BT*CC];   // LN1 out
__device__ f16   g_qb [BT*CC];   // [B,H,T,D], pre-scaled by 0.125*log2(e)
__device__ f16   g_kb [BT*CC];
__device__ f16   g_vb [BT*CC];
__device__ f16   g_ap1[BT*CC];   // attention partial O (key lower half), unnormalized fp16
__device__ f16   g_ap2[BT*CC];   // attention partial O (key upper half), unnormalized fp16
__device__ float g_lp1[BB*HH*TT];// partial row sums l (lower half) [bh][t]
__device__ float g_lp2[BB*HH*TT];// partial row sums l (upper half)
__device__ f16   g_h2b[BT*CC];   // LN2 out
__device__ f16   g_wqb[HH*CC*DD];
__device__ f16   g_wkb[HH*CC*DD];
__device__ f16   g_wvb[HH*CC*DD];
__device__ f16   g_wfb[CC*CC];

#define LOG2E 1.44269504f
#define ONES32 0x3C003C00u   // half2(1,1)

// ---------------- PTX helpers ----------------
__device__ __forceinline__ unsigned smem_u32(const void* p) {
    return (unsigned)__cvta_generic_to_shared(p);
}
__device__ __forceinline__ void ldsm_x4(unsigned (&r)[4], unsigned a) {
    asm volatile("ldmatrix.sync.aligned.m8n8.x4.shared.b16 {%0,%1,%2,%3}, [%4];"
                 : "=r"(r[0]), "=r"(r[1]), "=r"(r[2]), "=r"(r[3]) : "r"(a));
}
__device__ __forceinline__ void ldsm_x4_t(unsigned (&r)[4], unsigned a) {
    asm volatile("ldmatrix.sync.aligned.m8n8.x4.trans.shared.b16 {%0,%1,%2,%3}, [%4];"
                 : "=r"(r[0]), "=r"(r[1]), "=r"(r[2]), "=r"(r[3]) : "r"(a));
}
__device__ __forceinline__ void mma_f16(float (&c)[4], const unsigned (&a)[4], unsigned b0, unsigned b1) {
    asm volatile("mma.sync.aligned.m16n8k16.row.col.f32.f16.f16.f32 "
                 "{%0,%1,%2,%3},{%4,%5,%6,%7},{%8,%9},{%0,%1,%2,%3};"
                 : "+f"(c[0]), "+f"(c[1]), "+f"(c[2]), "+f"(c[3])
                 : "r"(a[0]), "r"(a[1]), "r"(a[2]), "r"(a[3]), "r"(b0), "r"(b1));
}
// fp16-accumulated MMA: D/C are packed half2 pairs (2 regs)
__device__ __forceinline__ void mma_h16(unsigned (&c)[2], const unsigned (&a)[4], unsigned b0, unsigned b1) {
    asm volatile("mma.sync.aligned.m16n8k16.row.col.f16.f16.f16.f16 "
                 "{%0,%1},{%2,%3,%4,%5},{%6,%7},{%0,%1};"
                 : "+r"(c[0]), "+r"(c[1])
                 : "r"(a[0]), "r"(a[1]), "r"(a[2]), "r"(a[3]), "r"(b0), "r"(b1));
}
__device__ __forceinline__ unsigned pack_f16(float lo, float hi) {
    __half2 v = __floats2half2_rn(lo, hi);
    unsigned u;
    memcpy(&u, &v, 4);
    return u;
}
__device__ __forceinline__ unsigned cvt_f16x2(float hi, float lo) {
    unsigned u;
    asm("cvt.rn.f16x2.f32 %0, %1, %2;" : "=r"(u) : "f"(hi), "f"(lo));
    return u;
}
__device__ __forceinline__ unsigned hex2(unsigned x) {
    unsigned y;
    asm("ex2.approx.f16x2 %0, %1;" : "=r"(y) : "r"(x));
    return y;
}
__device__ __forceinline__ void cp16(unsigned dst, const void* src) {
    asm volatile("cp.async.cg.shared.global [%0], [%1], 16;" :: "r"(dst), "l"(src));
}
__device__ __forceinline__ void cp_commit() {
    asm volatile("cp.async.commit_group;");
}
template <int N>
__device__ __forceinline__ void cp_wait() {
    asm volatile("cp.async.wait_group %0;" :: "n"(N));
}

// ---------------- weight conversion ----------------
__global__ __launch_bounds__(256) void conv_w(const float* __restrict__ wq,
                                              const float* __restrict__ wk,
                                              const float* __restrict__ wv,
                                              const float* __restrict__ wf) {
    int i = blockIdx.x * 256 + threadIdx.x;
    g_wqb[i] = __float2half(wq[i]);
    g_wkb[i] = __float2half(wk[i]);
    g_wvb[i] = __float2half(wv[i]);
    g_wfb[i] = __float2half(wf[i]);
}

// ---------------- LN1 ----------------
__global__ __launch_bounds__(128) void ln1_kernel(const float* __restrict__ x,
                                                  const float* __restrict__ lng,
                                                  const float* __restrict__ lnb) {
    int row = blockIdx.x;
    int tid = threadIdx.x;
    float4 v = ((const float4*)(x + (size_t)row*CC))[tid];
    float s  = v.x + v.y + v.z + v.w;
    float s2 = v.x*v.x + v.y*v.y + v.z*v.z + v.w*v.w;
    __shared__ float red[8];
    #pragma unroll
    for (int m = 16; m > 0; m >>= 1) {
        s  += __shfl_xor_sync(0xffffffffu, s,  m);
        s2 += __shfl_xor_sync(0xffffffffu, s2, m);
    }
    int w = tid >> 5;
    if ((tid & 31) == 0) { red[w] = s; red[4 + w] = s2; }
    __syncthreads();
    s  = red[0] + red[1] + red[2] + red[3];
    s2 = red[4] + red[5] + red[6] + red[7];
    float mu  = s * (1.0f / CC);
    float var = s2 * (1.0f / CC) - mu * mu;
    float rsd = rsqrtf(var + 1e-5f);
    float4 gvec = ((const float4*)lng)[tid];
    float4 bvec = ((const float4*)lnb)[tid];
    __half2* out_row = (__half2*)(g_hb + (size_t)row*CC);
    out_row[tid*2+0] = __floats2half2_rn((v.x-mu)*rsd*gvec.x+bvec.x, (v.y-mu)*rsd*gvec.y+bvec.y);
    out_row[tid*2+1] = __floats2half2_rn((v.z-mu)*rsd*gvec.z+bvec.z, (v.w-mu)*rsd*gvec.w+bvec.w);
}

// ---------------- QKV projection: per-matrix blocks, M=32/warp ----------------
// grid (BT/128, H, 3), 128 threads (4 warps); z selects q/k/v.
__global__ __launch_bounds__(128, 3) void qkv_kernel() {
    extern __shared__ f16 smA[];
    const int BUF = (128 + 64) * WP;     // A tile (128 rows) + W tile (64 rows)
    int t0   = blockIdx.x * 128;
    int head = blockIdx.y;
    int mat  = blockIdx.z;
    int tid  = threadIdx.x, warp = tid >> 5, lane = tid & 31;

    const f16* wptr = (mat == 0 ? g_wqb : (mat == 1 ? g_wkb : g_wvb)) + (size_t)head*CC*DD;
    f16*       optr = (mat == 0 ? g_qb  : (mat == 1 ? g_kb  : g_vb));

    float ac0[8][4] = {}, ac1[8][4] = {};
    int brow_in = (((lane >> 3) & 1) << 3) + (lane & 7);
    int bcol_in = ((lane >> 4) << 3);

    {
        f16* dA = smA;
        for (int it = tid; it < 1024; it += 128) {
            int r = it >> 3, c8 = (it & 7) * 8;
            cp16(smem_u32(dA + r*WP + c8), g_hb + (size_t)(t0 + r)*CC + c8);
        }
        f16* dW = smA + 128*WP;
        for (int it = tid; it < 512; it += 128) {
            int r = it >> 3, c8 = (it & 7) * 8;
            cp16(smem_u32(dW + r*WP + c8), wptr + (size_t)r*DD + c8);
        }
        cp_commit();
    }

    int m0 = warp * 32;
    for (int ch = 0; ch < 8; ch++) {
        if (ch + 1 < 8) {
            int kc = (ch + 1) * 64;
            f16* dA = smA + ((ch + 1) & 1) * BUF;
            for (int it = tid; it < 1024; it += 128) {
                int r = it >> 3, c8 = (it & 7) * 8;
                cp16(smem_u32(dA + r*WP + c8), g_hb + (size_t)(t0 + r)*CC + kc + c8);
            }
            f16* dW = dA + 128*WP;
            for (int it = tid; it < 512; it += 128) {
                int r = it >> 3, c8 = (it & 7) * 8;
                cp16(smem_u32(dW + r*WP + c8), wptr + (size_t)(kc + r)*DD + c8);
            }
            cp_commit();
            cp_wait<1>();
        } else {
            cp_wait<0>();
        }
        __syncthreads();
        f16* cb_ = smA + (ch & 1) * BUF;
        unsigned aB = smem_u32(cb_), wB = smem_u32(cb_ + 128*WP);
        #pragma unroll
        for (int kk = 0; kk < 4; kk++) {
            unsigned af0[4], af1[4];
            {
                int row = m0 + (lane & 7) + (lane & 8);
                int col = kk*16 + ((lane >> 4) << 3);
                ldsm_x4(af0, aB + (unsigned)(row*WP + col) * 2);
                ldsm_x4(af1, aB + (unsigned)((row + 16)*WP + col) * 2);
            }
            #pragma unroll
            for (int nt2 = 0; nt2 < 4; nt2++) {
                unsigned b4[4];
                ldsm_x4_t(b4, wB + (unsigned)((kk*16 + brow_in)*WP + nt2*16 + bcol_in) * 2);
                mma_f16(ac0[2*nt2],   af0, b4[0], b4[1]);
                mma_f16(ac0[2*nt2+1], af0, b4[2], b4[3]);
                mma_f16(ac1[2*nt2],   af1, b4[0], b4[1]);
                mma_f16(ac1[2*nt2+1], af1, b4[2], b4[3]);
            }
        }
        __syncthreads();
    }
    int bI = t0 / TT, tl = t0 % TT;
    size_t base = ((size_t)(bI*HH + head)*TT + tl) * DD;
    int r0 = m0 + (lane >> 2);
    int cb = 2 * (lane & 3);
    const float sc = (mat == 0) ? (0.125f * LOG2E) : 1.0f;
    #pragma unroll
    for (int nt = 0; nt < 8; nt++) {
        int c = nt*8 + cb;
        *(unsigned*)(optr + base + (size_t)r0*DD + c)      = pack_f16(ac0[nt][0]*sc, ac0[nt][1]*sc);
        *(unsigned*)(optr + base + (size_t)(r0+8)*DD + c)  = pack_f16(ac0[nt][2]*sc, ac0[nt][3]*sc);
        *(unsigned*)(optr + base + (size_t)(r0+16)*DD + c) = pack_f16(ac1[nt][0]*sc, ac1[nt][1]*sc);
        *(unsigned*)(optr + base + (size_t)(r0+24)*DD + c) = pack_f16(ac1[nt][2]*sc, ac1[nt][3]*sc);
    }
}

// ---------------- flash attention: split-K, fp16 O ACCUMULATORS, 4 blocks/SM ----------------
// grid (32, B*H), 128 threads (4 warps, M=32/warp); double-buffered K/V.
__global__ __launch_bounds__(128, 4) void attn_kernel() {
    extern __shared__ f16 smB[];
    f16* sQ = smB;                       // [q 128][d 64]
    f16* sK = smB + 128*WP;              // 2 x [key 64][d 64]
    f16* sV = smB + 128*WP + 2*64*WP;    // 2 x [key 64][d 64]
    int idx = blockIdx.x;                // 0..31, longest work first
    int st   = 15 - (idx >> 1);
    int half = idx & 1;
    int bh = blockIdx.y;
    const f16* qp = g_qb + (size_t)bh*TT*DD;
    const f16* kp = g_kb + (size_t)bh*TT*DD;
    const f16* vp = g_vb + (size_t)bh*TT*DD;
    f16*       op = (half ? g_ap2 : g_ap1) + (size_t)bh*TT*DD;
    float*     lp = (half ? g_lp2 : g_lp1) + (size_t)bh*TT;

    int tid = threadIdx.x, warp = tid >> 5, lane = tid & 31;
    int q0 = st * 128;
    int j0 = half ? (st + 1) : 0;
    int j1 = half ? (2*st + 2) : (st + 1);
    unsigned qB = smem_u32(sQ);

    for (int it = tid; it < 1024; it += 128) {
        int r = it >> 3, c8 = (it & 7) * 8;
        *(uint4*)(sQ + r*WP + c8) = *(const uint4*)(qp + (size_t)(q0 + r)*DD + c8);
    }
    {
        const f16* kp_t = kp + (size_t)j0*64*DD;
        const f16* vp_t = vp + (size_t)j0*64*DD;
        for (int it = tid; it < 512; it += 128) {
            int r = it >> 3, c8 = (it & 7) * 8;
            cp16(smem_u32(sK + r*WP + c8), kp_t + (size_t)r*DD + c8);
            cp16(smem_u32(sV + r*WP + c8), vp_t + (size_t)r*DD + c8);
        }
        cp_commit();
    }

    unsigned o0[8][2] = {}, o1[8][2] = {};   // fp16x2 accumulators (zero = +0h2)
    float l0[4] = {}, l1[4] = {};
    unsigned qf0[4][4], qf1[4][4];
    int m0 = warp * 32;
    int rq = lane >> 2;
    int cb = 2 * (lane & 3);
    int brow_in = (((lane >> 3) & 1) << 3) + (lane & 7);
    int bcol_in = ((lane >> 4) << 3);

    for (int jt = j0; jt < j1; jt++) {
        int k0 = jt * 64;
        int cur = (jt - j0) & 1;
        if (jt + 1 < j1) {
            int nb = (jt + 1 - j0) & 1;
            f16* dK = sK + nb*64*WP; f16* dV = sV + nb*64*WP;
            const f16* kp_t = kp + (size_t)(jt+1)*64*DD;
            const f16* vp_t = vp + (size_t)(jt+1)*64*DD;
            for (int it = tid; it < 512; it += 128) {
                int r = it >> 3, c8 = (it & 7) * 8;
                cp16(smem_u32(dK + r*WP + c8), kp_t + (size_t)r*DD + c8);
                cp16(smem_u32(dV + r*WP + c8), vp_t + (size_t)r*DD + c8);
            }
            cp_commit();
            cp_wait<1>();
        } else {
            cp_wait<0>();
        }
        __syncthreads();
        if (jt == j0) {
            #pragma unroll
            for (int kk = 0; kk < 4; kk++) {
                int row = m0 + (lane & 7) + (lane & 8);
                int col = kk*16 + ((lane >> 4) << 3);
                ldsm_x4(qf0[kk], qB + (unsigned)(row*WP + col) * 2);
                ldsm_x4(qf1[kk], qB + (unsigned)((row + 16)*WP + col) * 2);
            }
        }
        unsigned kBc = smem_u32(sK + cur*64*WP);
        unsigned vBc = smem_u32(sV + cur*64*WP);
        bool active = (k0 <= q0 + m0 + 31);
        bool diag   = (k0 + 63 > q0 + m0);

        if (active) {
            // fused per-16-key chunk: S(fp32) -> mask -> P(fp16) -> ones-MMA(fp32 l) -> PV(fp16 acc)
            #pragma unroll
            for (int j = 0; j < 4; j++) {
                float s0a[4] = {}, s0b[4] = {}, s1a[4] = {}, s1b[4] = {};
                #pragma unroll
                for (int kk = 0; kk < 4; kk++) {
                    unsigned b4[4];
                    ldsm_x4(b4, kBc + (unsigned)((j*16 + brow_in)*WP + kk*16 + bcol_in) * 2);
                    mma_f16(s0a, qf0[kk], b4[0], b4[2]);
                    mma_f16(s0b, qf0[kk], b4[1], b4[3]);
                    mma_f16(s1a, qf1[kk], b4[0], b4[2]);
                    mma_f16(s1b, qf1[kk], b4[1], b4[3]);
                }
                if (diag) {
                    int rg0 = q0 + m0 + rq;
                    int rg1 = rg0 + 16;
                    int ca = k0 + j*16 + cb;
                    int cbv = ca + 8;
                    if (ca      > rg0)     s0a[0] = -30000.f;
                    if (ca + 1  > rg0)     s0a[1] = -30000.f;
                    if (ca      > rg0 + 8) s0a[2] = -30000.f;
                    if (ca + 1  > rg0 + 8) s0a[3] = -30000.f;
                    if (cbv     > rg0)     s0b[0] = -30000.f;
                    if (cbv + 1 > rg0)     s0b[1] = -30000.f;
                    if (cbv     > rg0 + 8) s0b[2] = -30000.f;
                    if (cbv + 1 > rg0 + 8) s0b[3] = -30000.f;
                    if (ca      > rg1)     s1a[0] = -30000.f;
                    if (ca + 1  > rg1)     s1a[1] = -30000.f;
                    if (ca      > rg1 + 8) s1a[2] = -30000.f;
                    if (ca + 1  > rg1 + 8) s1a[3] = -30000.f;
                    if (cbv     > rg1)     s1b[0] = -30000.f;
                    if (cbv + 1 > rg1)     s1b[1] = -30000.f;
                    if (cbv     > rg1 + 8) s1b[2] = -30000.f;
                    if (cbv + 1 > rg1 + 8) s1b[3] = -30000.f;
                }
                unsigned pf0[4], pf1[4];
                pf0[0] = hex2(cvt_f16x2(s0a[1], s0a[0]));
                pf0[1] = hex2(cvt_f16x2(s0a[3], s0a[2]));
                pf0[2] = hex2(cvt_f16x2(s0b[1], s0b[0]));
                pf0[3] = hex2(cvt_f16x2(s0b[3], s0b[2]));
                pf1[0] = hex2(cvt_f16x2(s1a[1], s1a[0]));
                pf1[1] = hex2(cvt_f16x2(s1a[3], s1a[2]));
                pf1[2] = hex2(cvt_f16x2(s1b[1], s1b[0]));
                pf1[3] = hex2(cvt_f16x2(s1b[3], s1b[2]));
                mma_f16(l0, pf0, ONES32, ONES32);
                mma_f16(l1, pf1, ONES32, ONES32);
                #pragma unroll
                for (int nd2 = 0; nd2 < 4; nd2++) {
                    unsigned b4[4];
                    ldsm_x4_t(b4, vBc + (unsigned)((j*16 + brow_in)*WP + nd2*16 + bcol_in) * 2);
                    mma_h16(o0[2*nd2],   pf0, b4[0], b4[1]);
                    mma_h16(o0[2*nd2+1], pf0, b4[2], b4[3]);
                    mma_h16(o1[2*nd2],   pf1, b4[0], b4[1]);
                    mma_h16(o1[2*nd2+1], pf1, b4[2], b4[3]);
                }
            }
        }
        __syncthreads();
    }

    // write UNNORMALIZED fp16 partial O (accumulators already packed) + fp32 l
    int r0 = q0 + m0 + rq;
    #pragma unroll
    for (int nd = 0; nd < 8; nd++) {
        int c = nd*8 + cb;
        *(unsigned*)(op + (size_t)r0*DD + c)      = o0[nd][0];
        *(unsigned*)(op + (size_t)(r0+8)*DD + c)  = o0[nd][1];
        *(unsigned*)(op + (size_t)(r0+16)*DD + c) = o1[nd][0];
        *(unsigned*)(op + (size_t)(r0+24)*DD + c) = o1[nd][1];
    }
    if ((lane & 3) == 0) {
        lp[r0]      = l0[0];
        lp[r0 + 8]  = l0[2];
        lp[r0 + 16] = l1[0];
        lp[r0 + 24] = l1[2];
    }
}

// ---------------- residual + split-K combine + LN2 ----------------
__global__ __launch_bounds__(128) void res_ln2_kernel(const float* __restrict__ x,
                                                      const float* __restrict__ lng,
                                                      const float* __restrict__ lnb,
                                                      float* __restrict__ out) {
    int row = blockIdx.x;
    int bI = row / TT, t = row % TT;
    int tid = threadIdx.x;
    int c = tid * 4;
    int h = c >> 6, d = c & 63;
    size_t bh = (size_t)(bI*HH + h);
    size_t aoff = (bh*TT + t)*DD + d;
    float4 xv = *(const float4*)(x + (size_t)row*CC + c);
    uint2 u1 = *(const uint2*)(g_ap1 + aoff);
    uint2 u2 = *(const uint2*)(g_ap2 + aoff);
    __half2 h1a = *(__half2*)&u1.x, h1b = *(__half2*)&u1.y;
    __half2 h2a = *(__half2*)&u2.x, h2b2 = *(__half2*)&u2.y;
    float2 f1a = __half22float2(h1a), f1b = __half22float2(h1b);
    float2 f2a = __half22float2(h2a), f2b = __half22float2(h2b2);
    float inv = 1.0f / (g_lp1[bh*TT + t] + g_lp2[bh*TT + t]);
    float4 v;
    v.x = xv.x + (f1a.x + f2a.x) * inv;
    v.y = xv.y + (f1a.y + f2a.y) * inv;
    v.z = xv.z + (f1b.x + f2b.x) * inv;
    v.w = xv.w + (f1b.y + f2b.y) * inv;
    *(float4*)(out + (size_t)row*CC + c) = v;

    float s  = v.x + v.y + v.z + v.w;
    float s2 = v.x*v.x + v.y*v.y + v.z*v.z + v.w*v.w;
    __shared__ float red2[8];
    #pragma unroll
    for (int mm = 16; mm > 0; mm >>= 1) {
        s  += __shfl_xor_sync(0xffffffffu, s,  mm);
        s2 += __shfl_xor_sync(0xffffffffu, s2, mm);
    }
    int w = tid >> 5;
    if ((tid & 31) == 0) { red2[w] = s; red2[4 + w] = s2; }
    __syncthreads();
    s  = red2[0] + red2[1] + red2[2] + red2[3];
    s2 = red2[4] + red2[5] + red2[6] + red2[7];
    float mu  = s * (1.0f / CC);
    float var = s2 * (1.0f / CC) - mu * mu;
    float rsd = rsqrtf(var + 1e-5f);
    float4 gvec = ((const float4*)lng)[tid];
    float4 bvec = ((const float4*)lnb)[tid];
    __half2* out_row2 = (__half2*)(g_h2b + (size_t)row*CC);
    out_row2[tid*2+0] = __floats2half2_rn((v.x-mu)*rsd*gvec.x+bvec.x, (v.y-mu)*rsd*gvec.y+bvec.y);
    out_row2[tid*2+1] = __floats2half2_rn((v.z-mu)*rsd*gvec.z+bvec.z, (v.w-mu)*rsd*gvec.w+bvec.w);
}

// ---------------- FFN: M=32/warp, cp.async double-buffered ----------------
// grid (C/64, BT/128), 128 threads (4 warps); out = x2 + relu(h2 @ W + b)
__global__ __launch_bounds__(128, 3) void ff_kernel(const float* __restrict__ bias,
                                                    float* __restrict__ out) {
    extern __shared__ f16 smC[];
    const int BUF = (128 + 64) * WP;
    int c0 = blockIdx.x * 64, r0 = blockIdx.y * 128;
    int tid = threadIdx.x, warp = tid >> 5, lane = tid & 31;
    int brow_in = (((lane >> 3) & 1) << 3) + (lane & 7);
    int bcol_in = ((lane >> 4) << 3);

    float ac0[8][4] = {}, ac1[8][4] = {};
    {
        f16* dA = smC;
        for (int it = tid; it < 1024; it += 128) {
            int r = it >> 3, c8 = (it & 7) * 8;
            cp16(smem_u32(dA + r*WP + c8), g_h2b + (size_t)(r0 + r)*CC + c8);
        }
        f16* dW = smC + 128*WP;
        for (int it = tid; it < 512; it += 128) {
            int r = it >> 3, c8 = (it & 7) * 8;
            cp16(smem_u32(dW + r*WP + c8), g_wfb + (size_t)r*CC + c0 + c8);
        }
        cp_commit();
    }
    int m0 = warp * 32;
    for (int ch = 0; ch < 8; ch++) {
        if (ch + 1 < 8) {
            int kc = (ch + 1) * 64;
            f16* dA = smC + ((ch + 1) & 1) * BUF;
            for (int it = tid; it < 1024; it += 128) {
                int r = it >> 3, c8 = (it & 7) * 8;
                cp16(smem_u32(dA + r*WP + c8), g_h2b + (size_t)(r0 + r)*CC + kc + c8);
            }
            f16* dW = dA + 128*WP;
            for (int it = tid; it < 512; it += 128) {
                int r = it >> 3, c8 = (it & 7) * 8;
                cp16(smem_u32(dW + r*WP + c8), g_wfb + (size_t)(kc + r)*CC + c0 + c8);
            }
            cp_commit();
            cp_wait<1>();
        } else {
            cp_wait<0>();
        }
        __syncthreads();
        f16* cb_ = smC + (ch & 1) * BUF;
        unsigned aB = smem_u32(cb_), wB = smem_u32(cb_ + 128*WP);
        #pragma unroll
        for (int kk = 0; kk < 4; kk++) {
            unsigned af0[4], af1[4];
            {
                int row = m0 + (lane & 7) + (lane & 8);
                int col = kk*16 + ((lane >> 4) << 3);
                ldsm_x4(af0, aB + (unsigned)(row*WP + col) * 2);
                ldsm_x4(af1, aB + (unsigned)((row + 16)*WP + col) * 2);
            }
            #pragma unroll
            for (int nt2 = 0; nt2 < 4; nt2++) {
                unsigned b4[4];
                ldsm_x4_t(b4, wB + (unsigned)((kk*16 + brow_in)*WP + nt2*16 + bcol_in) * 2);
                mma_f16(ac0[2*nt2],   af0, b4[0], b4[1]);
                mma_f16(ac0[2*nt2+1], af0, b4[2], b4[3]);
                mma_f16(ac1[2*nt2],   af1, b4[0], b4[1]);
                mma_f16(ac1[2*nt2+1], af1, b4[2], b4[3]);
            }
        }
        __syncthreads();
    }
    int rr = r0 + m0 + (lane >> 2);
    int cbl = 2 * (lane & 3);
    #pragma unroll
    for (int nt = 0; nt < 8; nt++) {
        int cg = c0 + nt*8 + cbl;
        float2 bv = *(const float2*)(bias + cg);
        size_t of0 = (size_t)rr*CC + cg;
        size_t of1 = (size_t)(rr+8)*CC + cg;
        size_t of2 = (size_t)(rr+16)*CC + cg;
        size_t of3 = (size_t)(rr+24)*CC + cg;
        float2 x0 = *(float2*)(out + of0);
        float2 x1 = *(float2*)(out + of1);
        float2 x2 = *(float2*)(out + of2);
        float2 x3 = *(float2*)(out + of3);
        x0.x += fmaxf(ac0[nt][0] + bv.x, 0.f);
        x0.y += fmaxf(ac0[nt][1] + bv.y, 0.f);
        x1.x += fmaxf(ac0[nt][2] + bv.x, 0.f);
        x1.y += fmaxf(ac0[nt][3] + bv.y, 0.f);
        x2.x += fmaxf(ac1[nt][0] + bv.x, 0.f);
        x2.y += fmaxf(ac1[nt][1] + bv.y, 0.f);
        x3.x += fmaxf(ac1[nt][2] + bv.x, 0.f);
        x3.y += fmaxf(ac1[nt][3] + bv.y, 0.f);
        *(float2*)(out + of0) = x0;
        *(float2*)(out + of1) = x1;
        *(float2*)(out + of2) = x2;
        *(float2*)(out + of3) = x3;
    }
}

// ---------------- launch ----------------
extern "C" void kernel_launch(void* const* d_in, const int* in_sizes, int n_in,
                              void* d_out, int out_size) {
    const float* x     = (const float*)d_in[0];
    const float* wq    = (const float*)d_in[1];
    const float* wk    = (const float*)d_in[2];
    const float* wv    = (const float*)d_in[3];
    const float* w_ff  = (const float*)d_in[4];
    const float* b_ff  = (const float*)d_in[5];
    const float* ln1_g = (const float*)d_in[6];
    const float* ln1_b = (const float*)d_in[7];
    const float* ln2_g = (const float*)d_in[8];
    const float* ln2_b = (const float*)d_in[9];
    float* out = (float*)d_out;

    const int attn_smem = (128 + 4*64) * WP * 2;       // 55296 B (4 blocks/SM fit)
    const int gemm_smem = 2 * (128 + 64) * WP * 2;     // 55296 B
    cudaFuncSetAttribute(attn_kernel, cudaFuncAttributeMaxDynamicSharedMemorySize, attn_smem);
    cudaFuncSetAttribute(qkv_kernel,  cudaFuncAttributeMaxDynamicSharedMemorySize, gemm_smem);
    cudaFuncSetAttribute(ff_kernel,   cudaFuncAttributeMaxDynamicSharedMemorySize, gemm_smem);

    conv_w<<<1024, 256>>>(wq, wk, wv, w_ff);
    ln1_kernel<<<BT, 128>>>(x, ln1_g, ln1_b);
    qkv_kernel<<<dim3(BT/128, HH, 3), 128, gemm_smem>>>();
    attn_kernel<<<dim3(32, BB*HH), 128, attn_smem>>>();
    res_ln2_kernel<<<BT, 128>>>(x, ln2_g, ln2_b, out);
    ff_kernel<<<dim3(CC/64, BT/128), 128, gemm_smem>>>(b_ff, out);
}

// round 16
// speedup vs baseline: 1.0055x; 1.0055x over previous
#include <cuda_runtime.h>
#include <cuda_fp16.h>
#include <stdint.h>
#include <math.h>

#define BB 4
#define TT 2048
#define CC 512
#define HH 8
#define DD 64
#define BT (BB*TT)
#define WP 72   // fp16 smem pitch for 64-wide tiles (144B rows: 16B aligned)

typedef __half  f16;

// -------- scratch (static device globals; no allocations allowed) --------
__device__ f16   g_hb [BT*CC];   // LN1 out
__device__ f16   g_qb [BT*CC];   // [B,H,T,D], pre-scaled by 0.125*log2(e)
__device__ f16   g_kb [BT*CC];
__device__ f16   g_vb [BT*CC];
__device__ f16   g_ap1[BT*CC];   // attention partial O (key lower half), unnormalized fp16
__device__ f16   g_ap2[BT*CC];   // attention partial O (key upper half), unnormalized fp16
__device__ float g_lp1[BB*HH*TT];// partial row sums l (lower half) [bh][t]
__device__ float g_lp2[BB*HH*TT];// partial row sums l (upper half)
__device__ f16   g_h2b[BT*CC];   // LN2 out
__device__ f16   g_wqb[HH*CC*DD];
__device__ f16   g_wkb[HH*CC*DD];
__device__ f16   g_wvb[HH*CC*DD];
__device__ f16   g_wfb[CC*CC];

#define LOG2E 1.44269504f
#define ONES32 0x3C003C00u   // half2(1,1)

// ---------------- PTX helpers ----------------
__device__ __forceinline__ unsigned smem_u32(const void* p) {
    return (unsigned)__cvta_generic_to_shared(p);
}
__device__ __forceinline__ void ldsm_x4(unsigned (&r)[4], unsigned a) {
    asm volatile("ldmatrix.sync.aligned.m8n8.x4.shared.b16 {%0,%1,%2,%3}, [%4];"
                 : "=r"(r[0]), "=r"(r[1]), "=r"(r[2]), "=r"(r[3]) : "r"(a));
}
__device__ __forceinline__ void ldsm_x4_t(unsigned (&r)[4], unsigned a) {
    asm volatile("ldmatrix.sync.aligned.m8n8.x4.trans.shared.b16 {%0,%1,%2,%3}, [%4];"
                 : "=r"(r[0]), "=r"(r[1]), "=r"(r[2]), "=r"(r[3]) : "r"(a));
}
__device__ __forceinline__ void mma_f16(float (&c)[4], const unsigned (&a)[4], unsigned b0, unsigned b1) {
    asm volatile("mma.sync.aligned.m16n8k16.row.col.f32.f16.f16.f32 "
                 "{%0,%1,%2,%3},{%4,%5,%6,%7},{%8,%9},{%0,%1,%2,%3};"
                 : "+f"(c[0]), "+f"(c[1]), "+f"(c[2]), "+f"(c[3])
                 : "r"(a[0]), "r"(a[1]), "r"(a[2]), "r"(a[3]), "r"(b0), "r"(b1));
}
// fp16-accumulated MMA: D/C are packed half2 pairs (2 regs)
__device__ __forceinline__ void mma_h16(unsigned (&c)[2], const unsigned (&a)[4], unsigned b0, unsigned b1) {
    asm volatile("mma.sync.aligned.m16n8k16.row.col.f16.f16.f16.f16 "
                 "{%0,%1},{%2,%3,%4,%5},{%6,%7},{%0,%1};"
                 : "+r"(c[0]), "+r"(c[1])
                 : "r"(a[0]), "r"(a[1]), "r"(a[2]), "r"(a[3]), "r"(b0), "r"(b1));
}
__device__ __forceinline__ unsigned pack_f16(float lo, float hi) {
    __half2 v = __floats2half2_rn(lo, hi);
    unsigned u;
    memcpy(&u, &v, 4);
    return u;
}
__device__ __forceinline__ unsigned cvt_f16x2(float hi, float lo) {
    unsigned u;
    asm("cvt.rn.f16x2.f32 %0, %1, %2;" : "=r"(u) : "f"(hi), "f"(lo));
    return u;
}
__device__ __forceinline__ unsigned hex2(unsigned x) {
    unsigned y;
    asm("ex2.approx.f16x2 %0, %1;" : "=r"(y) : "r"(x));
    return y;
}
__device__ __forceinline__ void cp16(unsigned dst, const void* src) {
    asm volatile("cp.async.cg.shared.global [%0], [%1], 16;" :: "r"(dst), "l"(src));
}
__device__ __forceinline__ void cp_commit() {
    asm volatile("cp.async.commit_group;");
}
template <int N>
__device__ __forceinline__ void cp_wait() {
    asm volatile("cp.async.wait_group %0;" :: "n"(N));
}

// ---------------- weight conversion ----------------
__global__ __launch_bounds__(256) void conv_w(const float* __restrict__ wq,
                                              const float* __restrict__ wk,
                                              const float* __restrict__ wv,
                                              const float* __restrict__ wf) {
    int i = blockIdx.x * 256 + threadIdx.x;
    g_wqb[i] = __float2half(wq[i]);
    g_wkb[i] = __float2half(wk[i]);
    g_wvb[i] = __float2half(wv[i]);
    g_wfb[i] = __float2half(wf[i]);
}

// ---------------- LN1 ----------------
__global__ __launch_bounds__(128) void ln1_kernel(const float* __restrict__ x,
                                                  const float* __restrict__ lng,
                                                  const float* __restrict__ lnb) {
    int row = blockIdx.x;
    int tid = threadIdx.x;
    float4 v = ((const float4*)(x + (size_t)row*CC))[tid];
    float s  = v.x + v.y + v.z + v.w;
    float s2 = v.x*v.x + v.y*v.y + v.z*v.z + v.w*v.w;
    __shared__ float red[8];
    #pragma unroll
    for (int m = 16; m > 0; m >>= 1) {
        s  += __shfl_xor_sync(0xffffffffu, s,  m);
        s2 += __shfl_xor_sync(0xffffffffu, s2, m);
    }
    int w = tid >> 5;
    if ((tid & 31) == 0) { red[w] = s; red[4 + w] = s2; }
    __syncthreads();
    s  = red[0] + red[1] + red[2] + red[3];
    s2 = red[4] + red[5] + red[6] + red[7];
    float mu  = s * (1.0f / CC);
    float var = s2 * (1.0f / CC) - mu * mu;
    float rsd = rsqrtf(var + 1e-5f);
    float4 gvec = ((const float4*)lng)[tid];
    float4 bvec = ((const float4*)lnb)[tid];
    __half2* out_row = (__half2*)(g_hb + (size_t)row*CC);
    out_row[tid*2+0] = __floats2half2_rn((v.x-mu)*rsd*gvec.x+bvec.x, (v.y-mu)*rsd*gvec.y+bvec.y);
    out_row[tid*2+1] = __floats2half2_rn((v.z-mu)*rsd*gvec.z+bvec.z, (v.w-mu)*rsd*gvec.w+bvec.w);
}

// ---------------- QKV projection: per-matrix blocks, M=32/warp ----------------
// grid (BT/128, H, 3), 128 threads (4 warps); z selects q/k/v.
__global__ __launch_bounds__(128, 3) void qkv_kernel() {
    extern __shared__ f16 smA[];
    const int BUF = (128 + 64) * WP;     // A tile (128 rows) + W tile (64 rows)
    int t0   = blockIdx.x * 128;
    int head = blockIdx.y;
    int mat  = blockIdx.z;
    int tid  = threadIdx.x, warp = tid >> 5, lane = tid & 31;

    const f16* wptr = (mat == 0 ? g_wqb : (mat == 1 ? g_wkb : g_wvb)) + (size_t)head*CC*DD;
    f16*       optr = (mat == 0 ? g_qb  : (mat == 1 ? g_kb  : g_vb));

    float ac0[8][4] = {}, ac1[8][4] = {};
    int brow_in = (((lane >> 3) & 1) << 3) + (lane & 7);
    int bcol_in = ((lane >> 4) << 3);

    {
        f16* dA = smA;
        for (int it = tid; it < 1024; it += 128) {
            int r = it >> 3, c8 = (it & 7) * 8;
            cp16(smem_u32(dA + r*WP + c8), g_hb + (size_t)(t0 + r)*CC + c8);
        }
        f16* dW = smA + 128*WP;
        for (int it = tid; it < 512; it += 128) {
            int r = it >> 3, c8 = (it & 7) * 8;
            cp16(smem_u32(dW + r*WP + c8), wptr + (size_t)r*DD + c8);
        }
        cp_commit();
    }

    int m0 = warp * 32;
    for (int ch = 0; ch < 8; ch++) {
        if (ch + 1 < 8) {
            int kc = (ch + 1) * 64;
            f16* dA = smA + ((ch + 1) & 1) * BUF;
            for (int it = tid; it < 1024; it += 128) {
                int r = it >> 3, c8 = (it & 7) * 8;
                cp16(smem_u32(dA + r*WP + c8), g_hb + (size_t)(t0 + r)*CC + kc + c8);
            }
            f16* dW = dA + 128*WP;
            for (int it = tid; it < 512; it += 128) {
                int r = it >> 3, c8 = (it & 7) * 8;
                cp16(smem_u32(dW + r*WP + c8), wptr + (size_t)(kc + r)*DD + c8);
            }
            cp_commit();
            cp_wait<1>();
        } else {
            cp_wait<0>();
        }
        __syncthreads();
        f16* cb_ = smA + (ch & 1) * BUF;
        unsigned aB = smem_u32(cb_), wB = smem_u32(cb_ + 128*WP);
        #pragma unroll
        for (int kk = 0; kk < 4; kk++) {
            unsigned af0[4], af1[4];
            {
                int row = m0 + (lane & 7) + (lane & 8);
                int col = kk*16 + ((lane >> 4) << 3);
                ldsm_x4(af0, aB + (unsigned)(row*WP + col) * 2);
                ldsm_x4(af1, aB + (unsigned)((row + 16)*WP + col) * 2);
            }
            #pragma unroll
            for (int nt2 = 0; nt2 < 4; nt2++) {
                unsigned b4[4];
                ldsm_x4_t(b4, wB + (unsigned)((kk*16 + brow_in)*WP + nt2*16 + bcol_in) * 2);
                mma_f16(ac0[2*nt2],   af0, b4[0], b4[1]);
                mma_f16(ac0[2*nt2+1], af0, b4[2], b4[3]);
                mma_f16(ac1[2*nt2],   af1, b4[0], b4[1]);
                mma_f16(ac1[2*nt2+1], af1, b4[2], b4[3]);
            }
        }
        __syncthreads();
    }
    int bI = t0 / TT, tl = t0 % TT;
    size_t base = ((size_t)(bI*HH + head)*TT + tl) * DD;
    int r0 = m0 + (lane >> 2);
    int cb = 2 * (lane & 3);
    const float sc = (mat == 0) ? (0.125f * LOG2E) : 1.0f;
    #pragma unroll
    for (int nt = 0; nt < 8; nt++) {
        int c = nt*8 + cb;
        *(unsigned*)(optr + base + (size_t)r0*DD + c)      = pack_f16(ac0[nt][0]*sc, ac0[nt][1]*sc);
        *(unsigned*)(optr + base + (size_t)(r0+8)*DD + c)  = pack_f16(ac0[nt][2]*sc, ac0[nt][3]*sc);
        *(unsigned*)(optr + base + (size_t)(r0+16)*DD + c) = pack_f16(ac1[nt][0]*sc, ac1[nt][1]*sc);
        *(unsigned*)(optr + base + (size_t)(r0+24)*DD + c) = pack_f16(ac1[nt][2]*sc, ac1[nt][3]*sc);
    }
}

// ---------------- flash attention: split-K, TRIPLE-buffered K/V, fp16 O accumulators ----------------
// grid (32, B*H), 128 threads (4 warps, M=32/warp), 3 blocks/SM (smem-bound).
// Single __syncthreads per tile; fp16 PV accumulators free ~32 regs for scheduling.
__global__ __launch_bounds__(128, 3) void attn_kernel() {
    extern __shared__ f16 smB[];
    f16* sQ  = smB;                      // [q 128][d 64]
    f16* sKV = smB + 128*WP;             // 3 x ([key 64][d 64] K + [key 64][d 64] V)
    const int KVB = 2*64*WP;             // one K+V buffer
    int idx = blockIdx.x;                // 0..31, longest work first
    int st   = 15 - (idx >> 1);
    int half = idx & 1;
    int bh = blockIdx.y;
    const f16* qp = g_qb + (size_t)bh*TT*DD;
    const f16* kp = g_kb + (size_t)bh*TT*DD;
    const f16* vp = g_vb + (size_t)bh*TT*DD;
    f16*       op = (half ? g_ap2 : g_ap1) + (size_t)bh*TT*DD;
    float*     lp = (half ? g_lp2 : g_lp1) + (size_t)bh*TT;

    int tid = threadIdx.x, warp = tid >> 5, lane = tid & 31;
    int q0 = st * 128;
    int j0 = half ? (st + 1) : 0;
    int j1 = half ? (2*st + 2) : (st + 1);
    unsigned qB = smem_u32(sQ);

    for (int it = tid; it < 1024; it += 128) {
        int r = it >> 3, c8 = (it & 7) * 8;
        *(uint4*)(sQ + r*WP + c8) = *(const uint4*)(qp + (size_t)(q0 + r)*DD + c8);
    }
    {
        f16* dK = sKV; f16* dV = sKV + 64*WP;
        const f16* kp_t = kp + (size_t)j0*64*DD;
        const f16* vp_t = vp + (size_t)j0*64*DD;
        for (int it = tid; it < 512; it += 128) {
            int r = it >> 3, c8 = (it & 7) * 8;
            cp16(smem_u32(dK + r*WP + c8), kp_t + (size_t)r*DD + c8);
            cp16(smem_u32(dV + r*WP + c8), vp_t + (size_t)r*DD + c8);
        }
        cp_commit();
    }

    unsigned o0[8][2] = {}, o1[8][2] = {};   // fp16x2 PV accumulators
    float l0[4] = {}, l1[4] = {};
    unsigned qf0[4][4], qf1[4][4];
    int m0 = warp * 32;
    int rq = lane >> 2;
    int cb = 2 * (lane & 3);
    int brow_in = (((lane >> 3) & 1) << 3) + (lane & 7);
    int bcol_in = ((lane >> 4) << 3);

    int bufi = 0;                        // (jt - j0) % 3
    for (int jt = j0; jt < j1; jt++) {
        int k0 = jt * 64;
        if (jt + 1 < j1) {
            int nb = bufi + 1; if (nb == 3) nb = 0;
            f16* dK = sKV + nb*KVB; f16* dV = dK + 64*WP;
            const f16* kp_t = kp + (size_t)(jt+1)*64*DD;
            const f16* vp_t = vp + (size_t)(jt+1)*64*DD;
            for (int it = tid; it < 512; it += 128) {
                int r = it >> 3, c8 = (it & 7) * 8;
                cp16(smem_u32(dK + r*WP + c8), kp_t + (size_t)r*DD + c8);
                cp16(smem_u32(dV + r*WP + c8), vp_t + (size_t)r*DD + c8);
            }
            cp_commit();
            cp_wait<1>();
        } else {
            cp_wait<0>();
        }
        __syncthreads();   // single barrier: data for tile jt visible to all warps
        if (jt == j0) {
            #pragma unroll
            for (int kk = 0; kk < 4; kk++) {
                int row = m0 + (lane & 7) + (lane & 8);
                int col = kk*16 + ((lane >> 4) << 3);
                ldsm_x4(qf0[kk], qB + (unsigned)(row*WP + col) * 2);
                ldsm_x4(qf1[kk], qB + (unsigned)((row + 16)*WP + col) * 2);
            }
        }
        unsigned kBc = smem_u32(sKV + bufi*KVB);
        unsigned vBc = kBc + (unsigned)(64*WP) * 2;
        bool active = (k0 <= q0 + m0 + 31);
        bool diag   = (k0 + 63 > q0 + m0);

        if (active) {
            // fused per-16-key chunk: S(fp32) -> mask -> P(fp16) -> ones-MMA(fp32 l) -> PV(fp16 acc)
            #pragma unroll
            for (int j = 0; j < 4; j++) {
                float s0a[4] = {}, s0b[4] = {}, s1a[4] = {}, s1b[4] = {};
                #pragma unroll
                for (int kk = 0; kk < 4; kk++) {
                    unsigned b4[4];
                    ldsm_x4(b4, kBc + (unsigned)((j*16 + brow_in)*WP + kk*16 + bcol_in) * 2);
                    mma_f16(s0a, qf0[kk], b4[0], b4[2]);
                    mma_f16(s0b, qf0[kk], b4[1], b4[3]);
                    mma_f16(s1a, qf1[kk], b4[0], b4[2]);
                    mma_f16(s1b, qf1[kk], b4[1], b4[3]);
                }
                if (diag) {
                    int rg0 = q0 + m0 + rq;
                    int rg1 = rg0 + 16;
                    int ca = k0 + j*16 + cb;
                    int cbv = ca + 8;
                    if (ca      > rg0)     s0a[0] = -30000.f;
                    if (ca + 1  > rg0)     s0a[1] = -30000.f;
                    if (ca      > rg0 + 8) s0a[2] = -30000.f;
                    if (ca + 1  > rg0 + 8) s0a[3] = -30000.f;
                    if (cbv     > rg0)     s0b[0] = -30000.f;
                    if (cbv + 1 > rg0)     s0b[1] = -30000.f;
                    if (cbv     > rg0 + 8) s0b[2] = -30000.f;
                    if (cbv + 1 > rg0 + 8) s0b[3] = -30000.f;
                    if (ca      > rg1)     s1a[0] = -30000.f;
                    if (ca + 1  > rg1)     s1a[1] = -30000.f;
                    if (ca      > rg1 + 8) s1a[2] = -30000.f;
                    if (ca + 1  > rg1 + 8) s1a[3] = -30000.f;
                    if (cbv     > rg1)     s1b[0] = -30000.f;
                    if (cbv + 1 > rg1)     s1b[1] = -30000.f;
                    if (cbv     > rg1 + 8) s1b[2] = -30000.f;
                    if (cbv + 1 > rg1 + 8) s1b[3] = -30000.f;
                }
                unsigned pf0[4], pf1[4];
                pf0[0] = hex2(cvt_f16x2(s0a[1], s0a[0]));
                pf0[1] = hex2(cvt_f16x2(s0a[3], s0a[2]));
                pf0[2] = hex2(cvt_f16x2(s0b[1], s0b[0]));
                pf0[3] = hex2(cvt_f16x2(s0b[3], s0b[2]));
                pf1[0] = hex2(cvt_f16x2(s1a[1], s1a[0]));
                pf1[1] = hex2(cvt_f16x2(s1a[3], s1a[2]));
                pf1[2] = hex2(cvt_f16x2(s1b[1], s1b[0]));
                pf1[3] = hex2(cvt_f16x2(s1b[3], s1b[2]));
                mma_f16(l0, pf0, ONES32, ONES32);
                mma_f16(l1, pf1, ONES32, ONES32);
                #pragma unroll
                for (int nd2 = 0; nd2 < 4; nd2++) {
                    unsigned b4[4];
                    ldsm_x4_t(b4, vBc + (unsigned)((j*16 + brow_in)*WP + nd2*16 + bcol_in) * 2);
                    mma_h16(o0[2*nd2],   pf0, b4[0], b4[1]);
                    mma_h16(o0[2*nd2+1], pf0, b4[2], b4[3]);
                    mma_h16(o1[2*nd2],   pf1, b4[0], b4[1]);
                    mma_h16(o1[2*nd2+1], pf1, b4[2], b4[3]);
                }
            }
        }
        bufi++; if (bufi == 3) bufi = 0;
    }

    // write UNNORMALIZED fp16 partial O (accumulators already packed) + fp32 l
    int r0 = q0 + m0 + rq;
    #pragma unroll
    for (int nd = 0; nd < 8; nd++) {
        int c = nd*8 + cb;
        *(unsigned*)(op + (size_t)r0*DD + c)      = o0[nd][0];
        *(unsigned*)(op + (size_t)(r0+8)*DD + c)  = o0[nd][1];
        *(unsigned*)(op + (size_t)(r0+16)*DD + c) = o1[nd][0];
        *(unsigned*)(op + (size_t)(r0+24)*DD + c) = o1[nd][1];
    }
    if ((lane & 3) == 0) {
        lp[r0]      = l0[0];
        lp[r0 + 8]  = l0[2];
        lp[r0 + 16] = l1[0];
        lp[r0 + 24] = l1[2];
    }
}

// ---------------- residual + split-K combine + LN2 ----------------
__global__ __launch_bounds__(128) void res_ln2_kernel(const float* __restrict__ x,
                                                      const float* __restrict__ lng,
                                                      const float* __restrict__ lnb,
                                                      float* __restrict__ out) {
    int row = blockIdx.x;
    int bI = row / TT, t = row % TT;
    int tid = threadIdx.x;
    int c = tid * 4;
    int h = c >> 6, d = c & 63;
    size_t bh = (size_t)(bI*HH + h);
    size_t aoff = (bh*TT + t)*DD + d;
    float4 xv = *(const float4*)(x + (size_t)row*CC + c);
    uint2 u1 = *(const uint2*)(g_ap1 + aoff);
    uint2 u2 = *(const uint2*)(g_ap2 + aoff);
    __half2 h1a = *(__half2*)&u1.x, h1b = *(__half2*)&u1.y;
    __half2 h2a = *(__half2*)&u2.x, h2b2 = *(__half2*)&u2.y;
    float2 f1a = __half22float2(h1a), f1b = __half22float2(h1b);
    float2 f2a = __half22float2(h2a), f2b = __half22float2(h2b2);
    float inv = 1.0f / (g_lp1[bh*TT + t] + g_lp2[bh*TT + t]);
    float4 v;
    v.x = xv.x + (f1a.x + f2a.x) * inv;
    v.y = xv.y + (f1a.y + f2a.y) * inv;
    v.z = xv.z + (f1b.x + f2b.x) * inv;
    v.w = xv.w + (f1b.y + f2b.y) * inv;
    *(float4*)(out + (size_t)row*CC + c) = v;

    float s  = v.x + v.y + v.z + v.w;
    float s2 = v.x*v.x + v.y*v.y + v.z*v.z + v.w*v.w;
    __shared__ float red2[8];
    #pragma unroll
    for (int mm = 16; mm > 0; mm >>= 1) {
        s  += __shfl_xor_sync(0xffffffffu, s,  mm);
        s2 += __shfl_xor_sync(0xffffffffu, s2, mm);
    }
    int w = tid >> 5;
    if ((tid & 31) == 0) { red2[w] = s; red2[4 + w] = s2; }
    __syncthreads();
    s  = red2[0] + red2[1] + red2[2] + red2[3];
    s2 = red2[4] + red2[5] + red2[6] + red2[7];
    float mu  = s * (1.0f / CC);
    float var = s2 * (1.0f / CC) - mu * mu;
    float rsd = rsqrtf(var + 1e-5f);
    float4 gvec = ((const float4*)lng)[tid];
    float4 bvec = ((const float4*)lnb)[tid];
    __half2* out_row2 = (__half2*)(g_h2b + (size_t)row*CC);
    out_row2[tid*2+0] = __floats2half2_rn((v.x-mu)*rsd*gvec.x+bvec.x, (v.y-mu)*rsd*gvec.y+bvec.y);
    out_row2[tid*2+1] = __floats2half2_rn((v.z-mu)*rsd*gvec.z+bvec.z, (v.w-mu)*rsd*gvec.w+bvec.w);
}

// ---------------- FFN: M=32/warp, cp.async double-buffered ----------------
// grid (C/64, BT/128), 128 threads (4 warps); out = x2 + relu(h2 @ W + b)
__global__ __launch_bounds__(128, 3) void ff_kernel(const float* __restrict__ bias,
                                                    float* __restrict__ out) {
    extern __shared__ f16 smC[];
    const int BUF = (128 + 64) * WP;
    int c0 = blockIdx.x * 64, r0 = blockIdx.y * 128;
    int tid = threadIdx.x, warp = tid >> 5, lane = tid & 31;
    int brow_in = (((lane >> 3) & 1) << 3) + (lane & 7);
    int bcol_in = ((lane >> 4) << 3);

    float ac0[8][4] = {}, ac1[8][4] = {};
    {
        f16* dA = smC;
        for (int it = tid; it < 1024; it += 128) {
            int r = it >> 3, c8 = (it & 7) * 8;
            cp16(smem_u32(dA + r*WP + c8), g_h2b + (size_t)(r0 + r)*CC + c8);
        }
        f16* dW = smC + 128*WP;
        for (int it = tid; it < 512; it += 128) {
            int r = it >> 3, c8 = (it & 7) * 8;
            cp16(smem_u32(dW + r*WP + c8), g_wfb + (size_t)r*CC + c0 + c8);
        }
        cp_commit();
    }
    int m0 = warp * 32;
    for (int ch = 0; ch < 8; ch++) {
        if (ch + 1 < 8) {
            int kc = (ch + 1) * 64;
            f16* dA = smC + ((ch + 1) & 1) * BUF;
            for (int it = tid; it < 1024; it += 128) {
                int r = it >> 3, c8 = (it & 7) * 8;
                cp16(smem_u32(dA + r*WP + c8), g_h2b + (size_t)(r0 + r)*CC + kc + c8);
            }
            f16* dW = dA + 128*WP;
            for (int it = tid; it < 512; it += 128) {
                int r = it >> 3, c8 = (it & 7) * 8;
                cp16(smem_u32(dW + r*WP + c8), g_wfb + (size_t)(kc + r)*CC + c0 + c8);
            }
            cp_commit();
            cp_wait<1>();
        } else {
            cp_wait<0>();
        }
        __syncthreads();
        f16* cb_ = smC + (ch & 1) * BUF;
        unsigned aB = smem_u32(cb_), wB = smem_u32(cb_ + 128*WP);
        #pragma unroll
        for (int kk = 0; kk < 4; kk++) {
            unsigned af0[4], af1[4];
            {
                int row = m0 + (lane & 7) + (lane & 8);
                int col = kk*16 + ((lane >> 4) << 3);
                ldsm_x4(af0, aB + (unsigned)(row*WP + col) * 2);
                ldsm_x4(af1, aB + (unsigned)((row + 16)*WP + col) * 2);
            }
            #pragma unroll
            for (int nt2 = 0; nt2 < 4; nt2++) {
                unsigned b4[4];
                ldsm_x4_t(b4, wB + (unsigned)((kk*16 + brow_in)*WP + nt2*16 + bcol_in) * 2);
                mma_f16(ac0[2*nt2],   af0, b4[0], b4[1]);
                mma_f16(ac0[2*nt2+1], af0, b4[2], b4[3]);
                mma_f16(ac1[2*nt2],   af1, b4[0], b4[1]);
                mma_f16(ac1[2*nt2+1], af1, b4[2], b4[3]);
            }
        }
        __syncthreads();
    }
    int rr = r0 + m0 + (lane >> 2);
    int cbl = 2 * (lane & 3);
    #pragma unroll
    for (int nt = 0; nt < 8; nt++) {
        int cg = c0 + nt*8 + cbl;
        float2 bv = *(const float2*)(bias + cg);
        size_t of0 = (size_t)rr*CC + cg;
        size_t of1 = (size_t)(rr+8)*CC + cg;
        size_t of2 = (size_t)(rr+16)*CC + cg;
        size_t of3 = (size_t)(rr+24)*CC + cg;
        float2 x0 = *(float2*)(out + of0);
        float2 x1 = *(float2*)(out + of1);
        float2 x2 = *(float2*)(out + of2);
        float2 x3 = *(float2*)(out + of3);
        x0.x += fmaxf(ac0[nt][0] + bv.x, 0.f);
        x0.y += fmaxf(ac0[nt][1] + bv.y, 0.f);
        x1.x += fmaxf(ac0[nt][2] + bv.x, 0.f);
        x1.y += fmaxf(ac0[nt][3] + bv.y, 0.f);
        x2.x += fmaxf(ac1[nt][0] + bv.x, 0.f);
        x2.y += fmaxf(ac1[nt][1] + bv.y, 0.f);
        x3.x += fmaxf(ac1[nt][2] + bv.x, 0.f);
        x3.y += fmaxf(ac1[nt][3] + bv.y, 0.f);
        *(float2*)(out + of0) = x0;
        *(float2*)(out + of1) = x1;
        *(float2*)(out + of2) = x2;
        *(float2*)(out + of3) = x3;
    }
}

// ---------------- launch ----------------
extern "C" void kernel_launch(void* const* d_in, const int* in_sizes, int n_in,
                              void* d_out, int out_size) {
    const float* x     = (const float*)d_in[0];
    const float* wq    = (const float*)d_in[1];
    const float* wk    = (const float*)d_in[2];
    const float* wv    = (const float*)d_in[3];
    const float* w_ff  = (const float*)d_in[4];
    const float* b_ff  = (const float*)d_in[5];
    const float* ln1_g = (const float*)d_in[6];
    const float* ln1_b = (const float*)d_in[7];
    const float* ln2_g = (const float*)d_in[8];
    const float* ln2_b = (const float*)d_in[9];
    float* out = (float*)d_out;

    const int attn_smem = (128 + 6*64) * WP * 2;       // 73728 B (Q + 3x(K+V))
    const int gemm_smem = 2 * (128 + 64) * WP * 2;     // 55296 B
    cudaFuncSetAttribute(attn_kernel, cudaFuncAttributeMaxDynamicSharedMemorySize, attn_smem);
    cudaFuncSetAttribute(qkv_kernel,  cudaFuncAttributeMaxDynamicSharedMemorySize, gemm_smem);
    cudaFuncSetAttribute(ff_kernel,   cudaFuncAttributeMaxDynamicSharedMemorySize, gemm_smem);

    conv_w<<<1024, 256>>>(wq, wk, wv, w_ff);
    ln1_kernel<<<BT, 128>>>(x, ln1_g, ln1_b);
    qkv_kernel<<<dim3(BT/128, HH, 3), 128, gemm_smem>>>();
    attn_kernel<<<dim3(32, BB*HH), 128, attn_smem>>>();
    res_ln2_kernel<<<BT, 128>>>(x, ln2_g, ln2_b, out);
    ff_kernel<<<dim3(CC/64, BT/128), 128, gemm_smem>>>(b_ff, out);
}

// round 17
// speedup vs baseline: 1.0177x; 1.0121x over previous
#include <cuda_runtime.h>
#include <cuda_fp16.h>
#include <stdint.h>
#include <math.h>

#define BB 4
#define TT 2048
#define CC 512
#define HH 8
#define DD 64
#define BT (BB*TT)
#define WP 72   // fp16 smem pitch for 64-wide tiles (144B rows: 16B aligned)

typedef __half  f16;

// -------- scratch (static device globals; no allocations allowed) --------
__device__ f16   g_hb [BT*CC];   // LN1 out
__device__ f16   g_qb [BT*CC];   // [B,H,T,D], pre-scaled by 0.125*log2(e)
__device__ f16   g_kb [BT*CC];
__device__ f16   g_vb [BT*CC];
__device__ f16   g_ap1[BT*CC];   // attention partial O (key lower half), unnormalized fp16
__device__ f16   g_ap2[BT*CC];   // attention partial O (key upper half), unnormalized fp16
__device__ float g_lp1[BB*HH*TT];// partial row sums l (lower half) [bh][t]
__device__ float g_lp2[BB*HH*TT];// partial row sums l (upper half)
__device__ f16   g_h2b[BT*CC];   // LN2 out
__device__ f16   g_wqb[HH*CC*DD];
__device__ f16   g_wkb[HH*CC*DD];
__device__ f16   g_wvb[HH*CC*DD];
__device__ f16   g_wfb[CC*CC];

#define LOG2E 1.44269504f
#define ONES32 0x3C003C00u   // half2(1,1)

// ---------------- PTX helpers ----------------
__device__ __forceinline__ unsigned smem_u32(const void* p) {
    return (unsigned)__cvta_generic_to_shared(p);
}
__device__ __forceinline__ void ldsm_x4(unsigned (&r)[4], unsigned a) {
    asm volatile("ldmatrix.sync.aligned.m8n8.x4.shared.b16 {%0,%1,%2,%3}, [%4];"
                 : "=r"(r[0]), "=r"(r[1]), "=r"(r[2]), "=r"(r[3]) : "r"(a));
}
__device__ __forceinline__ void ldsm_x4_t(unsigned (&r)[4], unsigned a) {
    asm volatile("ldmatrix.sync.aligned.m8n8.x4.trans.shared.b16 {%0,%1,%2,%3}, [%4];"
                 : "=r"(r[0]), "=r"(r[1]), "=r"(r[2]), "=r"(r[3]) : "r"(a));
}
__device__ __forceinline__ void mma_f16(float (&c)[4], const unsigned (&a)[4], unsigned b0, unsigned b1) {
    asm volatile("mma.sync.aligned.m16n8k16.row.col.f32.f16.f16.f32 "
                 "{%0,%1,%2,%3},{%4,%5,%6,%7},{%8,%9},{%0,%1,%2,%3};"
                 : "+f"(c[0]), "+f"(c[1]), "+f"(c[2]), "+f"(c[3])
                 : "r"(a[0]), "r"(a[1]), "r"(a[2]), "r"(a[3]), "r"(b0), "r"(b1));
}
__device__ __forceinline__ unsigned pack_f16(float lo, float hi) {
    __half2 v = __floats2half2_rn(lo, hi);
    unsigned u;
    memcpy(&u, &v, 4);
    return u;
}
__device__ __forceinline__ unsigned cvt_f16x2(float hi, float lo) {
    unsigned u;
    asm("cvt.rn.f16x2.f32 %0, %1, %2;" : "=r"(u) : "f"(hi), "f"(lo));
    return u;
}
__device__ __forceinline__ unsigned hex2(unsigned x) {
    unsigned y;
    asm("ex2.approx.f16x2 %0, %1;" : "=r"(y) : "r"(x));
    return y;
}
__device__ __forceinline__ void cp16(unsigned dst, const void* src) {
    asm volatile("cp.async.cg.shared.global [%0], [%1], 16;" :: "r"(dst), "l"(src));
}
__device__ __forceinline__ void cp_commit() {
    asm volatile("cp.async.commit_group;");
}
template <int N>
__device__ __forceinline__ void cp_wait() {
    asm volatile("cp.async.wait_group %0;" :: "n"(N));
}

// ---------------- fused weight conversion + LN1 ----------------
// blocks [0,1024): convert 4x 262144 weights; blocks [1024,1024+BT/2): LN1, 2 rows/block.
__global__ __launch_bounds__(256) void conv_ln1_kernel(const float* __restrict__ wq,
                                                       const float* __restrict__ wk,
                                                       const float* __restrict__ wv,
                                                       const float* __restrict__ wf,
                                                       const float* __restrict__ x,
                                                       const float* __restrict__ lng,
                                                       const float* __restrict__ lnb) {
    if (blockIdx.x < 1024) {
        int i = blockIdx.x * 256 + threadIdx.x;
        g_wqb[i] = __float2half(wq[i]);
        g_wkb[i] = __float2half(wk[i]);
        g_wvb[i] = __float2half(wv[i]);
        g_wfb[i] = __float2half(wf[i]);
        return;
    }
    int row  = (blockIdx.x - 1024) * 2 + (threadIdx.x >> 7);
    int tid  = threadIdx.x & 127;
    int rsel = threadIdx.x >> 7;
    float4 v = ((const float4*)(x + (size_t)row*CC))[tid];
    float s  = v.x + v.y + v.z + v.w;
    float s2 = v.x*v.x + v.y*v.y + v.z*v.z + v.w*v.w;
    __shared__ float red[2][8];
    #pragma unroll
    for (int m = 16; m > 0; m >>= 1) {
        s  += __shfl_xor_sync(0xffffffffu, s,  m);
        s2 += __shfl_xor_sync(0xffffffffu, s2, m);
    }
    int wr = tid >> 5;
    if ((tid & 31) == 0) { red[rsel][wr] = s; red[rsel][4 + wr] = s2; }
    __syncthreads();
    s  = red[rsel][0] + red[rsel][1] + red[rsel][2] + red[rsel][3];
    s2 = red[rsel][4] + red[rsel][5] + red[rsel][6] + red[rsel][7];
    float mu  = s * (1.0f / CC);
    float var = s2 * (1.0f / CC) - mu * mu;
    float rsd = rsqrtf(var + 1e-5f);
    float4 gvec = ((const float4*)lng)[tid];
    float4 bvec = ((const float4*)lnb)[tid];
    __half2* out_row = (__half2*)(g_hb + (size_t)row*CC);
    out_row[tid*2+0] = __floats2half2_rn((v.x-mu)*rsd*gvec.x+bvec.x, (v.y-mu)*rsd*gvec.y+bvec.y);
    out_row[tid*2+1] = __floats2half2_rn((v.z-mu)*rsd*gvec.z+bvec.z, (v.w-mu)*rsd*gvec.w+bvec.w);
}

// ---------------- QKV projection: per-matrix blocks, M=32/warp ----------------
// grid (BT/128, H, 3), 128 threads (4 warps); z selects q/k/v.
__global__ __launch_bounds__(128, 3) void qkv_kernel() {
    extern __shared__ f16 smA[];
    const int BUF = (128 + 64) * WP;     // A tile (128 rows) + W tile (64 rows)
    int t0   = blockIdx.x * 128;
    int head = blockIdx.y;
    int mat  = blockIdx.z;
    int tid  = threadIdx.x, warp = tid >> 5, lane = tid & 31;

    const f16* wptr = (mat == 0 ? g_wqb : (mat == 1 ? g_wkb : g_wvb)) + (size_t)head*CC*DD;
    f16*       optr = (mat == 0 ? g_qb  : (mat == 1 ? g_kb  : g_vb));

    float ac0[8][4] = {}, ac1[8][4] = {};
    int brow_in = (((lane >> 3) & 1) << 3) + (lane & 7);
    int bcol_in = ((lane >> 4) << 3);

    {
        f16* dA = smA;
        for (int it = tid; it < 1024; it += 128) {
            int r = it >> 3, c8 = (it & 7) * 8;
            cp16(smem_u32(dA + r*WP + c8), g_hb + (size_t)(t0 + r)*CC + c8);
        }
        f16* dW = smA + 128*WP;
        for (int it = tid; it < 512; it += 128) {
            int r = it >> 3, c8 = (it & 7) * 8;
            cp16(smem_u32(dW + r*WP + c8), wptr + (size_t)r*DD + c8);
        }
        cp_commit();
    }

    int m0 = warp * 32;
    for (int ch = 0; ch < 8; ch++) {
        if (ch + 1 < 8) {
            int kc = (ch + 1) * 64;
            f16* dA = smA + ((ch + 1) & 1) * BUF;
            for (int it = tid; it < 1024; it += 128) {
                int r = it >> 3, c8 = (it & 7) * 8;
                cp16(smem_u32(dA + r*WP + c8), g_hb + (size_t)(t0 + r)*CC + kc + c8);
            }
            f16* dW = dA + 128*WP;
            for (int it = tid; it < 512; it += 128) {
                int r = it >> 3, c8 = (it & 7) * 8;
                cp16(smem_u32(dW + r*WP + c8), wptr + (size_t)(kc + r)*DD + c8);
            }
            cp_commit();
            cp_wait<1>();
        } else {
            cp_wait<0>();
        }
        __syncthreads();
        f16* cb_ = smA + (ch & 1) * BUF;
        unsigned aB = smem_u32(cb_), wB = smem_u32(cb_ + 128*WP);
        #pragma unroll
        for (int kk = 0; kk < 4; kk++) {
            unsigned af0[4], af1[4];
            {
                int row = m0 + (lane & 7) + (lane & 8);
                int col = kk*16 + ((lane >> 4) << 3);
                ldsm_x4(af0, aB + (unsigned)(row*WP + col) * 2);
                ldsm_x4(af1, aB + (unsigned)((row + 16)*WP + col) * 2);
            }
            #pragma unroll
            for (int nt2 = 0; nt2 < 4; nt2++) {
                unsigned b4[4];
                ldsm_x4_t(b4, wB + (unsigned)((kk*16 + brow_in)*WP + nt2*16 + bcol_in) * 2);
                mma_f16(ac0[2*nt2],   af0, b4[0], b4[1]);
                mma_f16(ac0[2*nt2+1], af0, b4[2], b4[3]);
                mma_f16(ac1[2*nt2],   af1, b4[0], b4[1]);
                mma_f16(ac1[2*nt2+1], af1, b4[2], b4[3]);
            }
        }
        __syncthreads();
    }
    int bI = t0 / TT, tl = t0 % TT;
    size_t base = ((size_t)(bI*HH + head)*TT + tl) * DD;
    int r0 = m0 + (lane >> 2);
    int cb = 2 * (lane & 3);
    const float sc = (mat == 0) ? (0.125f * LOG2E) : 1.0f;
    #pragma unroll
    for (int nt = 0; nt < 8; nt++) {
        int c = nt*8 + cb;
        *(unsigned*)(optr + base + (size_t)r0*DD + c)      = pack_f16(ac0[nt][0]*sc, ac0[nt][1]*sc);
        *(unsigned*)(optr + base + (size_t)(r0+8)*DD + c)  = pack_f16(ac0[nt][2]*sc, ac0[nt][3]*sc);
        *(unsigned*)(optr + base + (size_t)(r0+16)*DD + c) = pack_f16(ac1[nt][0]*sc, ac1[nt][1]*sc);
        *(unsigned*)(optr + base + (size_t)(r0+24)*DD + c) = pack_f16(ac1[nt][2]*sc, ac1[nt][3]*sc);
    }
}

// ---------------- flash attention: split-K, fp16 partial O, TRIPLE-buffered K/V ----------------
// grid (32, B*H), 128 threads (4 warps, M=32/warp), 3 blocks/SM.
// One __syncthreads per tile (3 buffers make the end-of-loop barrier unnecessary).
__global__ __launch_bounds__(128, 3) void attn_kernel() {
    extern __shared__ f16 smB[];
    f16* sQ  = smB;                      // [q 128][d 64]
    f16* sKV = smB + 128*WP;             // 3 x ([key 64][d 64] K + [key 64][d 64] V)
    const int KVB = 2*64*WP;             // one K+V buffer
    int idx = blockIdx.x;                // 0..31, longest work first
    int st   = 15 - (idx >> 1);
    int half = idx & 1;
    int bh = blockIdx.y;
    const f16* qp = g_qb + (size_t)bh*TT*DD;
    const f16* kp = g_kb + (size_t)bh*TT*DD;
    const f16* vp = g_vb + (size_t)bh*TT*DD;
    f16*       op = (half ? g_ap2 : g_ap1) + (size_t)bh*TT*DD;
    float*     lp = (half ? g_lp2 : g_lp1) + (size_t)bh*TT;

    int tid = threadIdx.x, warp = tid >> 5, lane = tid & 31;
    int q0 = st * 128;
    int j0 = half ? (st + 1) : 0;
    int j1 = half ? (2*st + 2) : (st + 1);
    unsigned qB = smem_u32(sQ);

    for (int it = tid; it < 1024; it += 128) {
        int r = it >> 3, c8 = (it & 7) * 8;
        *(uint4*)(sQ + r*WP + c8) = *(const uint4*)(qp + (size_t)(q0 + r)*DD + c8);
    }
    {
        f16* dK = sKV; f16* dV = sKV + 64*WP;
        const f16* kp_t = kp + (size_t)j0*64*DD;
        const f16* vp_t = vp + (size_t)j0*64*DD;
        for (int it = tid; it < 512; it += 128) {
            int r = it >> 3, c8 = (it & 7) * 8;
            cp16(smem_u32(dK + r*WP + c8), kp_t + (size_t)r*DD + c8);
            cp16(smem_u32(dV + r*WP + c8), vp_t + (size_t)r*DD + c8);
        }
        cp_commit();
    }

    float o0[8][4] = {}, o1[8][4] = {};
    float l0[4] = {}, l1[4] = {};
    unsigned qf0[4][4], qf1[4][4];
    int m0 = warp * 32;
    int rq = lane >> 2;
    int cb = 2 * (lane & 3);
    int brow_in = (((lane >> 3) & 1) << 3) + (lane & 7);
    int bcol_in = ((lane >> 4) << 3);

    int bufi = 0;                        // (jt - j0) % 3
    for (int jt = j0; jt < j1; jt++) {
        int k0 = jt * 64;
        if (jt + 1 < j1) {
            int nb = bufi + 1; if (nb == 3) nb = 0;
            f16* dK = sKV + nb*KVB; f16* dV = dK + 64*WP;
            const f16* kp_t = kp + (size_t)(jt+1)*64*DD;
            const f16* vp_t = vp + (size_t)(jt+1)*64*DD;
            for (int it = tid; it < 512; it += 128) {
                int r = it >> 3, c8 = (it & 7) * 8;
                cp16(smem_u32(dK + r*WP + c8), kp_t + (size_t)r*DD + c8);
                cp16(smem_u32(dV + r*WP + c8), vp_t + (size_t)r*DD + c8);
            }
            cp_commit();
            cp_wait<1>();
        } else {
            cp_wait<0>();
        }
        __syncthreads();   // single barrier: data for tile jt visible to all warps
        if (jt == j0) {
            #pragma unroll
            for (int kk = 0; kk < 4; kk++) {
                int row = m0 + (lane & 7) + (lane & 8);
                int col = kk*16 + ((lane >> 4) << 3);
                ldsm_x4(qf0[kk], qB + (unsigned)(row*WP + col) * 2);
                ldsm_x4(qf1[kk], qB + (unsigned)((row + 16)*WP + col) * 2);
            }
        }
        unsigned kBc = smem_u32(sKV + bufi*KVB);
        unsigned vBc = kBc + (unsigned)(64*WP) * 2;
        bool active = (k0 <= q0 + m0 + 31);
        bool diag   = (k0 + 63 > q0 + m0);

        if (active) {
            // fused per-16-key chunk: S -> mask -> P -> ones-MMA -> PV
            #pragma unroll
            for (int j = 0; j < 4; j++) {
                float s0a[4] = {}, s0b[4] = {}, s1a[4] = {}, s1b[4] = {};
                #pragma unroll
                for (int kk = 0; kk < 4; kk++) {
                    unsigned b4[4];
                    ldsm_x4(b4, kBc + (unsigned)((j*16 + brow_in)*WP + kk*16 + bcol_in) * 2);
                    mma_f16(s0a, qf0[kk], b4[0], b4[2]);
                    mma_f16(s0b, qf0[kk], b4[1], b4[3]);
                    mma_f16(s1a, qf1[kk], b4[0], b4[2]);
                    mma_f16(s1b, qf1[kk], b4[1], b4[3]);
                }
                if (diag) {
                    int rg0 = q0 + m0 + rq;
                    int rg1 = rg0 + 16;
                    int ca = k0 + j*16 + cb;
                    int cbv = ca + 8;
                    if (ca      > rg0)     s0a[0] = -30000.f;
                    if (ca + 1  > rg0)     s0a[1] = -30000.f;
                    if (ca      > rg0 + 8) s0a[2] = -30000.f;
                    if (ca + 1  > rg0 + 8) s0a[3] = -30000.f;
                    if (cbv     > rg0)     s0b[0] = -30000.f;
                    if (cbv + 1 > rg0)     s0b[1] = -30000.f;
                    if (cbv     > rg0 + 8) s0b[2] = -30000.f;
                    if (cbv + 1 > rg0 + 8) s0b[3] = -30000.f;
                    if (ca      > rg1)     s1a[0] = -30000.f;
                    if (ca + 1  > rg1)     s1a[1] = -30000.f;
                    if (ca      > rg1 + 8) s1a[2] = -30000.f;
                    if (ca + 1  > rg1 + 8) s1a[3] = -30000.f;
                    if (cbv     > rg1)     s1b[0] = -30000.f;
                    if (cbv + 1 > rg1)     s1b[1] = -30000.f;
                    if (cbv     > rg1 + 8) s1b[2] = -30000.f;
                    if (cbv + 1 > rg1 + 8) s1b[3] = -30000.f;
                }
                unsigned pf0[4], pf1[4];
                pf0[0] = hex2(cvt_f16x2(s0a[1], s0a[0]));
                pf0[1] = hex2(cvt_f16x2(s0a[3], s0a[2]));
                pf0[2] = hex2(cvt_f16x2(s0b[1], s0b[0]));
                pf0[3] = hex2(cvt_f16x2(s0b[3], s0b[2]));
                pf1[0] = hex2(cvt_f16x2(s1a[1], s1a[0]));
                pf1[1] = hex2(cvt_f16x2(s1a[3], s1a[2]));
                pf1[2] = hex2(cvt_f16x2(s1b[1], s1b[0]));
                pf1[3] = hex2(cvt_f16x2(s1b[3], s1b[2]));
                mma_f16(l0, pf0, ONES32, ONES32);
                mma_f16(l1, pf1, ONES32, ONES32);
                #pragma unroll
                for (int nd2 = 0; nd2 < 4; nd2++) {
                    unsigned b4[4];
                    ldsm_x4_t(b4, vBc + (unsigned)((j*16 + brow_in)*WP + nd2*16 + bcol_in) * 2);
                    mma_f16(o0[2*nd2],   pf0, b4[0], b4[1]);
                    mma_f16(o0[2*nd2+1], pf0, b4[2], b4[3]);
                    mma_f16(o1[2*nd2],   pf1, b4[0], b4[1]);
                    mma_f16(o1[2*nd2+1], pf1, b4[2], b4[3]);
                }
            }
        }
        bufi++; if (bufi == 3) bufi = 0;
    }

    // write UNNORMALIZED fp16 partial O + fp32 l
    int r0 = q0 + m0 + rq;
    #pragma unroll
    for (int nd = 0; nd < 8; nd++) {
        int c = nd*8 + cb;
        *(unsigned*)(op + (size_t)r0*DD + c)      = pack_f16(o0[nd][0], o0[nd][1]);
        *(unsigned*)(op + (size_t)(r0+8)*DD + c)  = pack_f16(o0[nd][2], o0[nd][3]);
        *(unsigned*)(op + (size_t)(r0+16)*DD + c) = pack_f16(o1[nd][0], o1[nd][1]);
        *(unsigned*)(op + (size_t)(r0+24)*DD + c) = pack_f16(o1[nd][2], o1[nd][3]);
    }
    if ((lane & 3) == 0) {
        lp[r0]      = l0[0];
        lp[r0 + 8]  = l0[2];
        lp[r0 + 16] = l1[0];
        lp[r0 + 24] = l1[2];
    }
}

// ---------------- residual + split-K combine + LN2 ----------------
__global__ __launch_bounds__(128) void res_ln2_kernel(const float* __restrict__ x,
                                                      const float* __restrict__ lng,
                                                      const float* __restrict__ lnb,
                                                      float* __restrict__ out) {
    int row = blockIdx.x;
    int bI = row / TT, t = row % TT;
    int tid = threadIdx.x;
    int c = tid * 4;
    int h = c >> 6, d = c & 63;
    size_t bh = (size_t)(bI*HH + h);
    size_t aoff = (bh*TT + t)*DD + d;
    float4 xv = *(const float4*)(x + (size_t)row*CC + c);
    uint2 u1 = *(const uint2*)(g_ap1 + aoff);
    uint2 u2 = *(const uint2*)(g_ap2 + aoff);
    __half2 h1a = *(__half2*)&u1.x, h1b = *(__half2*)&u1.y;
    __half2 h2a = *(__half2*)&u2.x, h2b2 = *(__half2*)&u2.y;
    float2 f1a = __half22float2(h1a), f1b = __half22float2(h1b);
    float2 f2a = __half22float2(h2a), f2b = __half22float2(h2b2);
    float inv = 1.0f / (g_lp1[bh*TT + t] + g_lp2[bh*TT + t]);
    float4 v;
    v.x = xv.x + (f1a.x + f2a.x) * inv;
    v.y = xv.y + (f1a.y + f2a.y) * inv;
    v.z = xv.z + (f1b.x + f2b.x) * inv;
    v.w = xv.w + (f1b.y + f2b.y) * inv;
    *(float4*)(out + (size_t)row*CC + c) = v;

    float s  = v.x + v.y + v.z + v.w;
    float s2 = v.x*v.x + v.y*v.y + v.z*v.z + v.w*v.w;
    __shared__ float red2[8];
    #pragma unroll
    for (int mm = 16; mm > 0; mm >>= 1) {
        s  += __shfl_xor_sync(0xffffffffu, s,  mm);
        s2 += __shfl_xor_sync(0xffffffffu, s2, mm);
    }
    int w = tid >> 5;
    if ((tid & 31) == 0) { red2[w] = s; red2[4 + w] = s2; }
    __syncthreads();
    s  = red2[0] + red2[1] + red2[2] + red2[3];
    s2 = red2[4] + red2[5] + red2[6] + red2[7];
    float mu  = s * (1.0f / CC);
    float var = s2 * (1.0f / CC) - mu * mu;
    float rsd = rsqrtf(var + 1e-5f);
    float4 gvec = ((const float4*)lng)[tid];
    float4 bvec = ((const float4*)lnb)[tid];
    __half2* out_row2 = (__half2*)(g_h2b + (size_t)row*CC);
    out_row2[tid*2+0] = __floats2half2_rn((v.x-mu)*rsd*gvec.x+bvec.x, (v.y-mu)*rsd*gvec.y+bvec.y);
    out_row2[tid*2+1] = __floats2half2_rn((v.z-mu)*rsd*gvec.z+bvec.z, (v.w-mu)*rsd*gvec.w+bvec.w);
}

// ---------------- FFN: M=32/warp, cp.async double-buffered ----------------
// grid (C/64, BT/128), 128 threads (4 warps); out = x2 + relu(h2 @ W + b)
__global__ __launch_bounds__(128, 3) void ff_kernel(const float* __restrict__ bias,
                                                    float* __restrict__ out) {
    extern __shared__ f16 smC[];
    const int BUF = (128 + 64) * WP;
    int c0 = blockIdx.x * 64, r0 = blockIdx.y * 128;
    int tid = threadIdx.x, warp = tid >> 5, lane = tid & 31;
    int brow_in = (((lane >> 3) & 1) << 3) + (lane & 7);
    int bcol_in = ((lane >> 4) << 3);

    float ac0[8][4] = {}, ac1[8][4] = {};
    {
        f16* dA = smC;
        for (int it = tid; it < 1024; it += 128) {
            int r = it >> 3, c8 = (it & 7) * 8;
            cp16(smem_u32(dA + r*WP + c8), g_h2b + (size_t)(r0 + r)*CC + c8);
        }
        f16* dW = smC + 128*WP;
        for (int it = tid; it < 512; it += 128) {
            int r = it >> 3, c8 = (it & 7) * 8;
            cp16(smem_u32(dW + r*WP + c8), g_wfb + (size_t)r*CC + c0 + c8);
        }
        cp_commit();
    }
    int m0 = warp * 32;
    for (int ch = 0; ch < 8; ch++) {
        if (ch + 1 < 8) {
            int kc = (ch + 1) * 64;
            f16* dA = smC + ((ch + 1) & 1) * BUF;
            for (int it = tid; it < 1024; it += 128) {
                int r = it >> 3, c8 = (it & 7) * 8;
                cp16(smem_u32(dA + r*WP + c8), g_h2b + (size_t)(r0 + r)*CC + kc + c8);
            }
            f16* dW = dA + 128*WP;
            for (int it = tid; it < 512; it += 128) {
                int r = it >> 3, c8 = (it & 7) * 8;
                cp16(smem_u32(dW + r*WP + c8), g_wfb + (size_t)(kc + r)*CC + c0 + c8);
            }
            cp_commit();
            cp_wait<1>();
        } else {
            cp_wait<0>();
        }
        __syncthreads();
        f16* cb_ = smC + (ch & 1) * BUF;
        unsigned aB = smem_u32(cb_), wB = smem_u32(cb_ + 128*WP);
        #pragma unroll
        for (int kk = 0; kk < 4; kk++) {
            unsigned af0[4], af1[4];
            {
                int row = m0 + (lane & 7) + (lane & 8);
                int col = kk*16 + ((lane >> 4) << 3);
                ldsm_x4(af0, aB + (unsigned)(row*WP + col) * 2);
                ldsm_x4(af1, aB + (unsigned)((row + 16)*WP + col) * 2);
            }
            #pragma unroll
            for (int nt2 = 0; nt2 < 4; nt2++) {
                unsigned b4[4];
                ldsm_x4_t(b4, wB + (unsigned)((kk*16 + brow_in)*WP + nt2*16 + bcol_in) * 2);
                mma_f16(ac0[2*nt2],   af0, b4[0], b4[1]);
                mma_f16(ac0[2*nt2+1], af0, b4[2], b4[3]);
                mma_f16(ac1[2*nt2],   af1, b4[0], b4[1]);
                mma_f16(ac1[2*nt2+1], af1, b4[2], b4[3]);
            }
        }
        __syncthreads();
    }
    int rr = r0 + m0 + (lane >> 2);
    int cbl = 2 * (lane & 3);
    #pragma unroll
    for (int nt = 0; nt < 8; nt++) {
        int cg = c0 + nt*8 + cbl;
        float2 bv = *(const float2*)(bias + cg);
        size_t of0 = (size_t)rr*CC + cg;
        size_t of1 = (size_t)(rr+8)*CC + cg;
        size_t of2 = (size_t)(rr+16)*CC + cg;
        size_t of3 = (size_t)(rr+24)*CC + cg;
        float2 x0 = *(float2*)(out + of0);
        float2 x1 = *(float2*)(out + of1);
        float2 x2 = *(float2*)(out + of2);
        float2 x3 = *(float2*)(out + of3);
        x0.x += fmaxf(ac0[nt][0] + bv.x, 0.f);
        x0.y += fmaxf(ac0[nt][1] + bv.y, 0.f);
        x1.x += fmaxf(ac0[nt][2] + bv.x, 0.f);
        x1.y += fmaxf(ac0[nt][3] + bv.y, 0.f);
        x2.x += fmaxf(ac1[nt][0] + bv.x, 0.f);
        x2.y += fmaxf(ac1[nt][1] + bv.y, 0.f);
        x3.x += fmaxf(ac1[nt][2] + bv.x, 0.f);
        x3.y += fmaxf(ac1[nt][3] + bv.y, 0.f);
        *(float2*)(out + of0) = x0;
        *(float2*)(out + of1) = x1;
        *(float2*)(out + of2) = x2;
        *(float2*)(out + of3) = x3;
    }
}

// ---------------- launch ----------------
extern "C" void kernel_launch(void* const* d_in, const int* in_sizes, int n_in,
                              void* d_out, int out_size) {
    const float* x     = (const float*)d_in[0];
    const float* wq    = (const float*)d_in[1];
    const float* wk    = (const float*)d_in[2];
    const float* wv    = (const float*)d_in[3];
    const float* w_ff  = (const float*)d_in[4];
    const float* b_ff  = (const float*)d_in[5];
    const float* ln1_g = (const float*)d_in[6];
    const float* ln1_b = (const float*)d_in[7];
    const float* ln2_g = (const float*)d_in[8];
    const float* ln2_b = (const float*)d_in[9];
    float* out = (float*)d_out;

    const int attn_smem = (128 + 6*64) * WP * 2;       // 73728 B (Q + 3x(K+V))
    const int gemm_smem = 2 * (128 + 64) * WP * 2;     // 55296 B
    cudaFuncSetAttribute(attn_kernel, cudaFuncAttributeMaxDynamicSharedMemorySize, attn_smem);
    cudaFuncSetAttribute(qkv_kernel,  cudaFuncAttributeMaxDynamicSharedMemorySize, gemm_smem);
    cudaFuncSetAttribute(ff_kernel,   cudaFuncAttributeMaxDynamicSharedMemorySize, gemm_smem);

    conv_ln1_kernel<<<1024 + BT/2, 256>>>(wq, wk, wv, w_ff, x, ln1_g, ln1_b);
    qkv_kernel<<<dim3(BT/128, HH, 3), 128, gemm_smem>>>();
    attn_kernel<<<dim3(32, BB*HH), 128, attn_smem>>>();
    res_ln2_kernel<<<BT, 128>>>(x, ln2_g, ln2_b, out);
    ff_kernel<<<dim3(CC/64, BT/128), 128, gemm_smem>>>(b_ff, out);
}